// round 4
// baseline (speedup 1.0000x reference)
#include <cuda_runtime.h>
#include <math.h>
#include <stdint.h>

#define BB   4
#define LL   2048
#define DMM  256
#define HH   8
#define EE   32
#define NLAY 3
#define NF   16
#define MTOT (BB*LL)      // 8192
#define UU   40           // U = u = 40

// ---------------- device scratch (static, no runtime alloc) ----------------
__device__ float g_x   [MTOT*DMM];
__device__ float g_q   [MTOT*DMM];
__device__ float g_k   [MTOT*DMM];
__device__ float g_v   [MTOT*DMM];
__device__ float g_ctx [MTOT*DMM];
__device__ float g_tmp [MTOT*DMM];
__device__ float g_y16 [MTOT*NF];
__device__ int   g_idx [LL*UU];
__device__ float g_M   [BB*HH*LL];
__device__ int   g_top [BB*HH*UU];
__device__ float g_vmean[BB*HH*EE];
__device__ float g_upd [BB*HH*UU*EE];
__device__ float g_stats[2*DMM];
__device__ float g_wk  [3*DMM*DMM];

// ---------------- threefry2x32 (20 rounds) ----------------
__device__ __forceinline__ uint32_t rotl32(uint32_t v, int d){ return (v<<d)|(v>>(32-d)); }

__device__ __forceinline__ void tf2x32(uint32_t k0, uint32_t k1, uint32_t x0, uint32_t x1,
                                       uint32_t &o0, uint32_t &o1)
{
    uint32_t ks2 = k0 ^ k1 ^ 0x1BD11BDAu;
    x0 += k0; x1 += k1;
#define TFR(r) { x0 += x1; x1 = rotl32(x1,(r)); x1 ^= x0; }
    TFR(13) TFR(15) TFR(26) TFR(6)
    x0 += k1;  x1 += ks2 + 1u;
    TFR(17) TFR(29) TFR(16) TFR(24)
    x0 += ks2; x1 += k0 + 2u;
    TFR(13) TFR(15) TFR(26) TFR(6)
    x0 += k0;  x1 += k1 + 3u;
    TFR(17) TFR(29) TFR(16) TFR(24)
    x0 += k1;  x1 += ks2 + 4u;
    TFR(13) TFR(15) TFR(26) TFR(6)
    x0 += ks2; x1 += k0 + 5u;
#undef TFR
    o0 = x0; o1 = x1;
}

// idx = randint(fold_in(key(42), layer), (2048,40), 0, 2048)
// PARTITIONABLE threefry (modern JAX default):
//   rkey = tf((0,42), (0,layer))
//   split foldlike: k2 = tf(rkey, (0,1))  (both outputs form the key)
//   random_bits 32-bit: bits[f] = o0 ^ o1 of tf(k2, (0, f))   <-- the XOR!
//   span=2048 pow2 -> idx = bits & 2047
__global__ void idx_kernel(int layer)
{
    int f = blockIdx.x*blockDim.x + threadIdx.x;
    if (f >= LL*UU) return;
    uint32_t r0, r1, k2a, k2b, o0, o1;
    tf2x32(0u, 42u, 0u, (uint32_t)layer, r0, r1);   // rkey = fold_in(key(42), layer)
    tf2x32(r0, r1, 0u, 1u, k2a, k2b);               // k2 = split(rkey)[1]
    tf2x32(k2a, k2b, 0u, (uint32_t)f, o0, o1);      // bits1, bits2
    g_idx[f] = (int)((o0 ^ o1) & 2047u);
}

// ---------------- SGEMM: C[M,N] = A'[M,K] @ W[N,K]^T (+bias) (+=) -----------
#define BM 128
#define BN 128
#define BKK 8

__global__ __launch_bounds__(256) void sgemm_nt(
    const float* __restrict__ A, const float* __restrict__ W,
    const float* __restrict__ bias, float* __restrict__ C,
    int M, int N, int K, int shift, int accumulate)
{
    __shared__ float As[BKK][BM];
    __shared__ float Bs[BKK][BN];
    int m0 = blockIdx.y * BM;
    int n0 = blockIdx.x * BN;
    int tid = threadIdx.x;
    int tx = tid & 15, ty = tid >> 4;

    int arow = tid >> 1;            // 0..127
    int acol = (tid & 1) * 4;       // 0 or 4
    int mg = m0 + arow;
    int bi = mg >> 11, l = mg & 2047;
    int lsrc = (l + shift + LL) & 2047;
    const float* Arow = A + (size_t)((bi << 11) + lsrc) * K;
    const float* Wrow = W + (size_t)(n0 + arow) * K;

    float acc[8][8];
#pragma unroll
    for (int i=0;i<8;i++)
#pragma unroll
        for (int j=0;j<8;j++) acc[i][j] = 0.f;

    for (int k0 = 0; k0 < K; k0 += BKK) {
        float4 av = *(const float4*)(Arow + k0 + acol);
        float4 wv = *(const float4*)(Wrow + k0 + acol);
        As[acol+0][arow]=av.x; As[acol+1][arow]=av.y; As[acol+2][arow]=av.z; As[acol+3][arow]=av.w;
        Bs[acol+0][arow]=wv.x; Bs[acol+1][arow]=wv.y; Bs[acol+2][arow]=wv.z; Bs[acol+3][arow]=wv.w;
        __syncthreads();
#pragma unroll
        for (int kk = 0; kk < BKK; kk++) {
            float a[8], b[8];
            *(float4*)&a[0] = *(const float4*)&As[kk][ty*8];
            *(float4*)&a[4] = *(const float4*)&As[kk][ty*8+4];
            *(float4*)&b[0] = *(const float4*)&Bs[kk][tx*8];
            *(float4*)&b[4] = *(const float4*)&Bs[kk][tx*8+4];
#pragma unroll
            for (int i=0;i<8;i++)
#pragma unroll
                for (int j=0;j<8;j++) acc[i][j] = fmaf(a[i], b[j], acc[i][j]);
        }
        __syncthreads();
    }

#pragma unroll
    for (int i=0;i<8;i++) {
        int m = m0 + ty*8 + i;
        float* Crow = C + (size_t)m*N + n0 + tx*8;
#pragma unroll
        for (int jj=0; jj<8; jj+=4) {
            float4 v;
            v.x=acc[i][jj]; v.y=acc[i][jj+1]; v.z=acc[i][jj+2]; v.w=acc[i][jj+3];
            if (bias) {
                float4 bb = *(const float4*)(bias + n0 + tx*8 + jj);
                v.x+=bb.x; v.y+=bb.y; v.z+=bb.z; v.w+=bb.w;
            }
            if (accumulate) {
                float4 o = *(const float4*)(Crow + jj);
                v.x+=o.x; v.y+=o.y; v.z+=o.z; v.w+=o.w;
            }
            *(float4*)(Crow + jj) = v;
        }
    }
}

// ---------------- attention pieces ----------------
// M[b,h,l] = max_u qk - sum_u qk / Lk ; one warp per (b,h,l)
__global__ __launch_bounds__(256) void qkM_kernel()
{
    int warp = threadIdx.x >> 5, lane = threadIdx.x & 31;
    int r = blockIdx.x*8 + warp;          // ((b*8+h)*2048+l)
    int b = r >> 14;
    int h = (r >> 11) & 7;
    int l = r & 2047;
    float qv = g_q[(size_t)((b<<11)+l)*DMM + (h<<5) + lane];
    float mx = -1e30f, sm = 0.f;
#pragma unroll 4
    for (int u=0; u<UU; u++) {
        int ki = g_idx[l*UU+u];
        float kv = g_k[(size_t)((b<<11)+ki)*DMM + (h<<5) + lane];
        float p = qv*kv;
#pragma unroll
        for (int o=16;o;o>>=1) p += __shfl_xor_sync(0xffffffffu, p, o);
        mx = fmaxf(mx, p);
        sm += p;
    }
    if (lane==0) g_M[r] = mx - sm*(1.f/2048.f);
}

// top-40 per (b,h): iterative argmax, ties -> lowest index
__global__ __launch_bounds__(256) void topk_kernel()
{
    int bh = blockIdx.x;
    __shared__ float vals[LL];
    __shared__ float rv[256];
    __shared__ int   ri[256];
    int t = threadIdx.x;
    for (int i=t; i<LL; i+=256) vals[i] = g_M[(size_t)bh*LL + i];
    __syncthreads();
    for (int it=0; it<UU; it++) {
        float bv = -1e38f; int bix = 0x7fffffff;
        for (int i=t; i<LL; i+=256) {
            float v = vals[i];
            if (v > bv) { bv = v; bix = i; }
        }
        rv[t]=bv; ri[t]=bix;
        __syncthreads();
        for (int s=128; s; s>>=1) {
            if (t < s) {
                if (rv[t+s] > rv[t] || (rv[t+s]==rv[t] && ri[t+s]<ri[t])) { rv[t]=rv[t+s]; ri[t]=ri[t+s]; }
            }
            __syncthreads();
        }
        if (t==0) { g_top[bh*UU+it] = ri[0]; vals[ri[0]] = -1e38f; }
        __syncthreads();
    }
}

__global__ __launch_bounds__(256) void vmean_kernel()
{
    int bh = blockIdx.x; int b = bh>>3, h = bh&7;
    int warp = threadIdx.x>>5, lane = threadIdx.x&31;
    __shared__ float accs[8][EE];
    float acc = 0.f;
    for (int l=warp; l<LL; l+=8)
        acc += g_v[(size_t)((b<<11)+l)*DMM + (h<<5) + lane];
    accs[warp][lane] = acc;
    __syncthreads();
    if (warp==0) {
        float s = 0.f;
#pragma unroll
        for (int w=0; w<8; w++) s += accs[w][lane];
        g_vmean[bh*EE + lane] = s * (1.f/2048.f);
    }
}

// full attention for the 40 selected queries: one block per (b,h,u)
__global__ __launch_bounds__(256) void attn_kernel()
{
    int gb = blockIdx.x;            // B*H*UU
    int u  = gb % UU; int bh = gb / UU; int b = bh>>3, h = bh&7;
    __shared__ float p[LL];
    __shared__ float qs[EE];
    __shared__ float red[8];
    __shared__ float up[8][EE];
    int t = threadIdx.x, warp = t>>5, lane = t&31;
    int tq = g_top[bh*UU+u];
    if (t < EE) qs[t] = g_q[(size_t)((b<<11)+tq)*DMM + (h<<5) + t];
    __syncthreads();
    float q = qs[lane];
    float wmax = -1e30f;
    for (int l=warp; l<LL; l+=8) {
        float kv = g_k[(size_t)((b<<11)+l)*DMM + (h<<5) + lane];
        float s = q*kv;
#pragma unroll
        for (int o=16;o;o>>=1) s += __shfl_xor_sync(0xffffffffu, s, o);
        s *= 0.17677669529663688f;   // 1/sqrt(32)
        if (lane==0) p[l] = s;
        wmax = fmaxf(wmax, s);
    }
    if (lane==0) red[warp] = wmax;
    __syncthreads();
    float mx = red[0];
#pragma unroll
    for (int w=1; w<8; w++) mx = fmaxf(mx, red[w]);
    __syncthreads();
    float lsum = 0.f;
    for (int l=t; l<LL; l+=256) { float e = expf(p[l]-mx); p[l]=e; lsum+=e; }
#pragma unroll
    for (int o=16;o;o>>=1) lsum += __shfl_xor_sync(0xffffffffu, lsum, o);
    if (lane==0) red[warp] = lsum;
    __syncthreads();
    float tot = 0.f;
#pragma unroll
    for (int w=0; w<8; w++) tot += red[w];
    float inv = 1.f / tot;
    float acc = 0.f;
    for (int l=warp; l<LL; l+=8)
        acc += p[l]*g_v[(size_t)((b<<11)+l)*DMM + (h<<5) + lane];
    up[warp][lane] = acc;
    __syncthreads();
    if (warp==0) {
        float s = 0.f;
#pragma unroll
        for (int w=0; w<8; w++) s += up[w][lane];
        g_upd[((size_t)bh*UU+u)*EE + lane] = s * inv;
    }
}

__global__ void ctxfill_kernel()
{
    int i = blockIdx.x*blockDim.x + threadIdx.x;   // over MTOT*DMM
    int e = i & 31; int h = (i>>5) & 7; int bl = i >> 8; int b = bl >> 11;
    g_ctx[i] = g_vmean[(b*8+h)*EE + e];
}

__global__ void scatter_kernel()
{
    int gb = blockIdx.x; int u = gb % UU; int bh = gb / UU; int b = bh>>3, h = bh&7;
    int tq = g_top[bh*UU+u];
    int e = threadIdx.x;   // 32
    g_ctx[(size_t)((b<<11)+tq)*DMM + (h<<5) + e] = g_upd[((size_t)bh*UU+u)*EE + e];
}

// ---------------- layernorm / ffn / distill ----------------
__device__ __forceinline__ float block_reduce_sum_256(float v, float* red)
{
    int lane = threadIdx.x & 31, warp = threadIdx.x >> 5;
#pragma unroll
    for (int o=16;o;o>>=1) v += __shfl_xor_sync(0xffffffffu, v, o);
    __syncthreads();
    if (lane==0) red[warp] = v;
    __syncthreads();
    float s = red[0];
#pragma unroll
    for (int w=1; w<8; w++) s += red[w];
    return s;
}

__global__ __launch_bounds__(256) void add_ln_kernel(
    const float* __restrict__ a, const float* __restrict__ res,
    const float* __restrict__ g, const float* __restrict__ beta,
    float* __restrict__ out)
{
    __shared__ float red[8];
    int row = blockIdx.x, t = threadIdx.x;
    float v = a[(size_t)row*DMM + t];
    if (res) v += res[(size_t)row*DMM + t];
    float mean = block_reduce_sum_256(v, red) * (1.f/256.f);
    float d = v - mean;
    float var = block_reduce_sum_256(d*d, red) * (1.f/256.f);
    out[(size_t)row*DMM + t] = d * rsqrtf(var + 1e-5f) * g[t] + beta[t];
}

__global__ __launch_bounds__(256) void ffn1_kernel(
    const float* __restrict__ w, const float* __restrict__ b1)
{
    __shared__ float xs[DMM];
    int row = blockIdx.x, t = threadIdx.x;
    xs[t] = g_x[(size_t)row*DMM + t];
    __syncthreads();
    int warp = t>>5, lane = t&31;
    for (int n = warp; n < NF; n += 8) {
        float acc = 0.f;
        const float* wr = w + (size_t)n*DMM;
        for (int k=lane; k<DMM; k+=32) acc = fmaf(xs[k], wr[k], acc);
#pragma unroll
        for (int o=16;o;o>>=1) acc += __shfl_xor_sync(0xffffffffu, acc, o);
        if (lane==0) g_y16[(size_t)row*NF + n] = fmaxf(acc + b1[n], 0.f);
    }
}

__global__ __launch_bounds__(256) void ffn2_ln_kernel(
    const float* __restrict__ w2, const float* __restrict__ b2,
    const float* __restrict__ g, const float* __restrict__ beta)
{
    __shared__ float ys[NF];
    __shared__ float red[8];
    int row = blockIdx.x, t = threadIdx.x;
    if (t < NF) ys[t] = g_y16[(size_t)row*NF + t];
    __syncthreads();
    float acc = b2[t];
    const float* wr = w2 + (size_t)t*NF;
#pragma unroll
    for (int f=0; f<NF; f++) acc = fmaf(ys[f], wr[f], acc);
    float v = g_x[(size_t)row*DMM + t] + acc;
    float mean = block_reduce_sum_256(v, red) * (1.f/256.f);
    float d = v - mean;
    float var = block_reduce_sum_256(d*d, red) * (1.f/256.f);
    g_x[(size_t)row*DMM + t] = d * rsqrtf(var + 1e-5f) * g[t] + beta[t];
}

__global__ void repack_kernel(const float* __restrict__ dcw)
{
    int i = blockIdx.x*blockDim.x + threadIdx.x;   // 3*65536
    if (i >= 3*DMM*DMM) return;
    int kk = i / (DMM*DMM); int rem = i % (DMM*DMM);
    int c = rem / DMM, ci = rem % DMM;
    g_wk[i] = dcw[(size_t)(c*DMM+ci)*3 + kk];
}

__global__ __launch_bounds__(256) void stats_kernel()
{
    __shared__ float red[8];
    int c = blockIdx.x, t = threadIdx.x;
    float s = 0.f, s2 = 0.f;
    for (int r=t; r<MTOT; r+=256) {
        float v = g_tmp[(size_t)r*DMM + c];
        s += v; s2 += v*v;
    }
    s  = block_reduce_sum_256(s,  red);
    s2 = block_reduce_sum_256(s2, red);
    if (t==0) {
        float m = s * (1.f/8192.f);
        float var = s2 * (1.f/8192.f) - m*m;
        g_stats[c] = m;
        g_stats[DMM + c] = rsqrtf(var + 1e-5f);
    }
}

__global__ void bn_elu_kernel(const float* __restrict__ g, const float* __restrict__ beta)
{
    int i = blockIdx.x*blockDim.x + threadIdx.x;   // MTOT*DMM
    int c = i & 255;
    float z = (g_tmp[i] - g_stats[c]) * g_stats[DMM+c] * g[c] + beta[c];
    g_x[i] = z > 0.f ? z : expm1f(z);
}

// ---------------- host orchestration ----------------
static float* symaddr(const void* sym) {
    void* p = nullptr;
    cudaGetSymbolAddress(&p, sym);
    return (float*)p;
}

extern "C" void kernel_launch(void* const* d_in, const int* in_sizes, int n_in,
                              void* d_out, int out_size)
{
    const float* x    = (const float*)d_in[0];
    const float* wq   = (const float*)d_in[1];
    const float* bq   = (const float*)d_in[2];
    const float* wk   = (const float*)d_in[3];
    const float* bk   = (const float*)d_in[4];
    const float* wv   = (const float*)d_in[5];
    const float* bv   = (const float*)d_in[6];
    const float* wo   = (const float*)d_in[7];
    const float* bo   = (const float*)d_in[8];
    const float* c1w  = (const float*)d_in[9];
    const float* c1b  = (const float*)d_in[10];
    const float* c2w  = (const float*)d_in[11];
    const float* c2b  = (const float*)d_in[12];
    const float* ln1g = (const float*)d_in[13];
    const float* ln1b = (const float*)d_in[14];
    const float* ln2g = (const float*)d_in[15];
    const float* ln2b = (const float*)d_in[16];
    const float* dcw  = (const float*)d_in[17];
    const float* dcb  = (const float*)d_in[18];
    const float* bng  = (const float*)d_in[19];
    const float* bnb  = (const float*)d_in[20];
    const float* fng  = (const float*)d_in[21];
    const float* fnb  = (const float*)d_in[22];

    float* gx   = symaddr(g_x);
    float* gq   = symaddr(g_q);
    float* gk   = symaddr(g_k);
    float* gv   = symaddr(g_v);
    float* gctx = symaddr(g_ctx);
    float* gtmp = symaddr(g_tmp);
    float* gwk  = symaddr(g_wk);

    cudaMemcpyAsync(gx, x, (size_t)MTOT*DMM*sizeof(float), cudaMemcpyDeviceToDevice, 0);

    dim3 ggrid(DMM/BN, MTOT/BM);   // (2, 64)

    for (int i = 0; i < NLAY; i++) {
        size_t woff = (size_t)i*DMM*DMM, boff = (size_t)i*DMM;

        sgemm_nt<<<ggrid,256>>>(gx, wq+woff, bq+boff, gq, MTOT, DMM, DMM, 0, 0);
        sgemm_nt<<<ggrid,256>>>(gx, wk+woff, bk+boff, gk, MTOT, DMM, DMM, 0, 0);
        sgemm_nt<<<ggrid,256>>>(gx, wv+woff, bv+boff, gv, MTOT, DMM, DMM, 0, 0);

        idx_kernel<<<(LL*UU+255)/256,256>>>(i);
        qkM_kernel<<<BB*HH*LL/8,256>>>();
        topk_kernel<<<BB*HH,256>>>();
        vmean_kernel<<<BB*HH,256>>>();
        attn_kernel<<<BB*HH*UU,256>>>();
        ctxfill_kernel<<<MTOT*DMM/256,256>>>();
        scatter_kernel<<<BB*HH*UU,32>>>();

        sgemm_nt<<<ggrid,256>>>(gctx, wo+woff, bo+boff, gtmp, MTOT, DMM, DMM, 0, 0);
        add_ln_kernel<<<MTOT,256>>>(gx, gtmp, ln1g+boff, ln1b+boff, gx);

        ffn1_kernel<<<MTOT,256>>>(c1w + (size_t)i*NF*DMM, c1b + (size_t)i*NF);
        ffn2_ln_kernel<<<MTOT,256>>>(c2w + (size_t)i*DMM*NF, c2b+boff, ln2g+boff, ln2b+boff);

        if (i < NLAY-1) {
            repack_kernel<<<(3*DMM*DMM+255)/256,256>>>(dcw + (size_t)i*DMM*DMM*3);
            sgemm_nt<<<ggrid,256>>>(gx, gwk,             dcb+boff, gtmp, MTOT, DMM, DMM, -1, 0);
            sgemm_nt<<<ggrid,256>>>(gx, gwk +   DMM*DMM, nullptr,  gtmp, MTOT, DMM, DMM,  0, 1);
            sgemm_nt<<<ggrid,256>>>(gx, gwk + 2*DMM*DMM, nullptr,  gtmp, MTOT, DMM, DMM,  1, 1);
            stats_kernel<<<DMM,256>>>();
            bn_elu_kernel<<<MTOT*DMM/256,256>>>(bng+boff, bnb+boff);
        }
    }

    add_ln_kernel<<<MTOT,256>>>(gx, nullptr, fng, fnb, (float*)d_out);
}

// round 5
// speedup vs baseline: 1.2678x; 1.2678x over previous
#include <cuda_runtime.h>
#include <math.h>
#include <stdint.h>

#define BB   4
#define LL   2048
#define DMM  256
#define HH   8
#define EE   32
#define NLAY 3
#define NF   16
#define MTOT (BB*LL)      // 8192
#define UU   40

// ---------------- device scratch ----------------
__device__ float g_x   [MTOT*DMM];
__device__ float g_qkv [MTOT*768];      // fused q|k|v
__device__ float g_ctx [MTOT*DMM];
__device__ float g_tmp [MTOT*DMM];
__device__ float g_y16 [MTOT*NF];
__device__ int   g_idx [LL*UU];
__device__ float g_M   [BB*HH*LL];
__device__ int   g_top [BB*HH*UU];
__device__ float g_vmean[BB*HH*EE];
__device__ float g_upd [BB*HH*UU*EE];
__device__ float g_stats[2*DMM];
__device__ float g_wk  [3*DMM*DMM];
__device__ float g_wqkv[NLAY*768*DMM];
__device__ float g_bqkv[NLAY*768];

// ---------------- threefry2x32 (20 rounds) ----------------
__device__ __forceinline__ uint32_t rotl32(uint32_t v, int d){ return (v<<d)|(v>>(32-d)); }

__device__ __forceinline__ void tf2x32(uint32_t k0, uint32_t k1, uint32_t x0, uint32_t x1,
                                       uint32_t &o0, uint32_t &o1)
{
    uint32_t ks2 = k0 ^ k1 ^ 0x1BD11BDAu;
    x0 += k0; x1 += k1;
#define TFR(r) { x0 += x1; x1 = rotl32(x1,(r)); x1 ^= x0; }
    TFR(13) TFR(15) TFR(26) TFR(6)
    x0 += k1;  x1 += ks2 + 1u;
    TFR(17) TFR(29) TFR(16) TFR(24)
    x0 += ks2; x1 += k0 + 2u;
    TFR(13) TFR(15) TFR(26) TFR(6)
    x0 += k0;  x1 += k1 + 3u;
    TFR(17) TFR(29) TFR(16) TFR(24)
    x0 += k1;  x1 += ks2 + 4u;
    TFR(13) TFR(15) TFR(26) TFR(6)
    x0 += ks2; x1 += k0 + 5u;
#undef TFR
    o0 = x0; o1 = x1;
}

// partitionable threefry: bits[f] = o0^o1 of tf(k2,(0,f)); idx = bits & 2047
__global__ void idx_kernel(int layer)
{
    int f = blockIdx.x*blockDim.x + threadIdx.x;
    if (f >= LL*UU) return;
    uint32_t r0, r1, k2a, k2b, o0, o1;
    tf2x32(0u, 42u, 0u, (uint32_t)layer, r0, r1);
    tf2x32(r0, r1, 0u, 1u, k2a, k2b);
    tf2x32(k2a, k2b, 0u, (uint32_t)f, o0, o1);
    g_idx[f] = (int)((o0 ^ o1) & 2047u);
}

// ---------------- weight/bias packing for fused QKV ----------------
__global__ void pack_qkv(const float* __restrict__ wq, const float* __restrict__ wk,
                         const float* __restrict__ wv, const float* __restrict__ bq,
                         const float* __restrict__ bk, const float* __restrict__ bv)
{
    int i = blockIdx.x*blockDim.x + threadIdx.x;
    int total = NLAY*768*DMM;
    if (i < total) {
        int layer = i / (768*DMM);
        int rem = i % (768*DMM);
        int row = rem / DMM, col = rem % DMM;
        const float* src = row < 256 ? wq : (row < 512 ? wk : wv);
        g_wqkv[i] = src[(size_t)layer*DMM*DMM + (size_t)(row & 255)*DMM + col];
    }
    if (i < NLAY*768) {
        int layer = i / 768; int row = i % 768;
        const float* src = row < 256 ? bq : (row < 512 ? bk : bv);
        g_bqkv[i] = src[layer*DMM + (row & 255)];
    }
}

// ---------------- SGEMM v2: double-buffered, multi-pass (conv) --------------
// C[M, Nout] (+bias) = sum_p A_shift(p)[M,256] @ Wp[Nout,256]^T
// BM=128, BN=64, BK=16, 256 threads, 8x4 per-thread tile.
#define BM2 128
#define BN2 64
#define BK2 16

__global__ __launch_bounds__(256) void sgemm2(
    const float* __restrict__ A, const float* __restrict__ W,
    const float* __restrict__ bias, float* __restrict__ C,
    int npass, int shift_base)
{
    __shared__ float As[2][BK2][BM2+4];
    __shared__ float Bs[2][BK2][BN2+4];
    int ldc = gridDim.x * BN2;
    size_t pstr = (size_t)ldc * 256;    // pass stride in W
    int m0 = blockIdx.y * BM2;
    int n0 = blockIdx.x * BN2;
    int tid = threadIdx.x;
    int tx = tid & 15, ty = tid >> 4;

    int ar = tid >> 1;            // 0..127
    int ak = (tid & 1) * 4;       // 0 or 4
    int br = tid >> 2;            // 0..63
    int bk = (tid & 3) * 4;       // 0,4,8,12

    int mg = m0 + ar;
    int bbase = (mg >> 11) << 11;
    int lrow  = mg & 2047;
    const float* Wrow = W + (size_t)(n0 + br) * 256;

    float acc[8][4];
#pragma unroll
    for (int i=0;i<8;i++)
#pragma unroll
        for (int j=0;j<4;j++) acc[i][j] = 0.f;

    int NT = npass * 16;

    // prefetch tile 0
    float4 pa0, pa1, pb;
    {
        int p = 0, k0 = 0;
        const float* Ap = A + (size_t)(bbase + ((lrow + shift_base + p + 2048) & 2047)) * 256 + k0;
        pa0 = *(const float4*)(Ap + ak);
        pa1 = *(const float4*)(Ap + ak + 8);
        pb  = *(const float4*)(Wrow + (size_t)p*pstr + k0 + bk);
    }
    As[0][ak+0][ar]=pa0.x; As[0][ak+1][ar]=pa0.y; As[0][ak+2][ar]=pa0.z; As[0][ak+3][ar]=pa0.w;
    As[0][ak+8][ar]=pa1.x; As[0][ak+9][ar]=pa1.y; As[0][ak+10][ar]=pa1.z; As[0][ak+11][ar]=pa1.w;
    Bs[0][bk+0][br]=pb.x;  Bs[0][bk+1][br]=pb.y;  Bs[0][bk+2][br]=pb.z;  Bs[0][bk+3][br]=pb.w;
    __syncthreads();

    int s = 0;
    for (int t = 0; t < NT; t++) {
        float4 na0, na1, nb;
        bool more = (t+1 < NT);
        if (more) {
            int tt = t+1;
            int p = tt >> 4, k0 = (tt & 15) << 4;
            const float* Ap = A + (size_t)(bbase + ((lrow + shift_base + p + 2048) & 2047)) * 256 + k0;
            na0 = *(const float4*)(Ap + ak);
            na1 = *(const float4*)(Ap + ak + 8);
            nb  = *(const float4*)(Wrow + (size_t)p*pstr + k0 + bk);
        }
#pragma unroll
        for (int kk = 0; kk < BK2; kk++) {
            float4 a0 = *(const float4*)&As[s][kk][ty*8];
            float4 a1 = *(const float4*)&As[s][kk][ty*8+4];
            float4 b0 = *(const float4*)&Bs[s][kk][tx*4];
            float a[8] = {a0.x,a0.y,a0.z,a0.w,a1.x,a1.y,a1.z,a1.w};
            float b[4] = {b0.x,b0.y,b0.z,b0.w};
#pragma unroll
            for (int i=0;i<8;i++)
#pragma unroll
                for (int j=0;j<4;j++) acc[i][j] = fmaf(a[i], b[j], acc[i][j]);
        }
        if (more) {
            int sn = s ^ 1;
            As[sn][ak+0][ar]=na0.x; As[sn][ak+1][ar]=na0.y; As[sn][ak+2][ar]=na0.z; As[sn][ak+3][ar]=na0.w;
            As[sn][ak+8][ar]=na1.x; As[sn][ak+9][ar]=na1.y; As[sn][ak+10][ar]=na1.z; As[sn][ak+11][ar]=na1.w;
            Bs[sn][bk+0][br]=nb.x;  Bs[sn][bk+1][br]=nb.y;  Bs[sn][bk+2][br]=nb.z;  Bs[sn][bk+3][br]=nb.w;
            s = sn;
        }
        __syncthreads();
    }

    float4 bb = *(const float4*)(bias + n0 + tx*4);
#pragma unroll
    for (int i=0;i<8;i++) {
        int m = m0 + ty*8 + i;
        float4 v;
        v.x = acc[i][0] + bb.x;
        v.y = acc[i][1] + bb.y;
        v.z = acc[i][2] + bb.z;
        v.w = acc[i][3] + bb.w;
        *(float4*)(C + (size_t)m*ldc + n0 + tx*4) = v;
    }
}

// ---------------- attention pieces ----------------
// M[b,h,l] = max_u qk - sum_u qk / Lk ; one warp per (b,h,l)
__global__ __launch_bounds__(256) void qkM_kernel()
{
    int warp = threadIdx.x >> 5, lane = threadIdx.x & 31;
    int r = blockIdx.x*8 + warp;          // ((b*8+h)*2048+l)
    int b = r >> 14;
    int h = (r >> 11) & 7;
    int l = r & 2047;
    float qv = g_qkv[(size_t)((b<<11)+l)*768 + (h<<5) + lane];
    float mx = -1e30f, sm = 0.f;
#pragma unroll 4
    for (int u=0; u<UU; u++) {
        int ki = g_idx[l*UU+u];
        float kv = g_qkv[(size_t)((b<<11)+ki)*768 + 256 + (h<<5) + lane];
        float p = qv*kv;
#pragma unroll
        for (int o=16;o;o>>=1) p += __shfl_xor_sync(0xffffffffu, p, o);
        mx = fmaxf(mx, p);
        sm += p;
    }
    if (lane==0) g_M[r] = mx - sm*(1.f/2048.f);
}

// top-40 per (b,h): packed u64 argmax, ties -> lowest index
__global__ __launch_bounds__(256) void topk_kernel()
{
    int bh = blockIdx.x;
    __shared__ unsigned long long vals[LL];
    __shared__ unsigned long long wbest[8];
    int t = threadIdx.x, lane = t & 31, warp = t >> 5;
    for (int i=t; i<LL; i+=256) {
        unsigned u = __float_as_uint(g_M[(size_t)bh*LL + i]);
        u = u ^ ((u >> 31) ? 0xFFFFFFFFu : 0x80000000u);   // order-preserving map
        vals[i] = ((unsigned long long)u << 32) | (unsigned)(LL-1 - i);
    }
    __syncthreads();
    for (int it=0; it<UU; it++) {
        unsigned long long best = 0ull;
#pragma unroll
        for (int j=0;j<8;j++) {
            unsigned long long v = vals[t + j*256];
            best = v > best ? v : best;
        }
#pragma unroll
        for (int o=16;o;o>>=1) {
            unsigned long long v = __shfl_xor_sync(0xffffffffu, best, o);
            best = v > best ? v : best;
        }
        if (lane==0) wbest[warp] = best;
        __syncthreads();
        if (t==0) {
            unsigned long long b2 = wbest[0];
#pragma unroll
            for (int w=1; w<8; w++) b2 = wbest[w] > b2 ? wbest[w] : b2;
            int idx = (LL-1) - (int)(b2 & 0xFFFFFFFFu);
            g_top[bh*UU+it] = idx;
            vals[idx] = 0ull;
        }
        __syncthreads();
    }
}

__global__ __launch_bounds__(256) void vmean_kernel()
{
    int bh = blockIdx.x; int b = bh>>3, h = bh&7;
    int warp = threadIdx.x>>5, lane = threadIdx.x&31;
    __shared__ float accs[8][EE];
    float acc = 0.f;
    for (int l=warp; l<LL; l+=8)
        acc += g_qkv[(size_t)((b<<11)+l)*768 + 512 + (h<<5) + lane];
    accs[warp][lane] = acc;
    __syncthreads();
    if (warp==0) {
        float s = 0.f;
#pragma unroll
        for (int w=0; w<8; w++) s += accs[w][lane];
        g_vmean[bh*EE + lane] = s * (1.f/2048.f);
    }
}

// full attention for 4 selected queries per block: grid = 32 bh * 10 chunks
__global__ __launch_bounds__(256) void attn_kernel4()
{
    int gb = blockIdx.x;
    int uc = gb % 10; int bh = gb / 10; int b = bh>>3, h = bh&7;
    __shared__ float p4[4][LL];          // 32KB
    __shared__ float qs[4][EE];
    __shared__ float invs[4];
    __shared__ float up[8][4][EE];
    int t = threadIdx.x, warp = t>>5, lane = t&31;
    if (t < 128) {
        int qi = t >> 5;
        int tq = g_top[bh*UU + uc*4 + qi];
        qs[qi][lane] = g_qkv[(size_t)((b<<11)+tq)*768 + (h<<5) + lane];
    }
    __syncthreads();
    float q0 = qs[0][lane], q1 = qs[1][lane], q2 = qs[2][lane], q3 = qs[3][lane];
    const float scale = 0.17677669529663688f;   // 1/sqrt(32)
    for (int l = warp; l < LL; l += 8) {
        float kv = g_qkv[(size_t)((b<<11)+l)*768 + 256 + (h<<5) + lane];
        float s0 = q0*kv, s1 = q1*kv, s2 = q2*kv, s3 = q3*kv;
#pragma unroll
        for (int o=16;o;o>>=1) {
            s0 += __shfl_xor_sync(0xffffffffu, s0, o);
            s1 += __shfl_xor_sync(0xffffffffu, s1, o);
            s2 += __shfl_xor_sync(0xffffffffu, s2, o);
            s3 += __shfl_xor_sync(0xffffffffu, s3, o);
        }
        if (lane==0) { p4[0][l]=s0*scale; p4[1][l]=s1*scale; p4[2][l]=s2*scale; p4[3][l]=s3*scale; }
    }
    __syncthreads();
    if (warp < 4) {                       // softmax stats for query `warp`
        float m = -1e30f;
        for (int l=lane; l<LL; l+=32) m = fmaxf(m, p4[warp][l]);
#pragma unroll
        for (int o=16;o;o>>=1) m = fmaxf(m, __shfl_xor_sync(0xffffffffu, m, o));
        float s = 0.f;
        for (int l=lane; l<LL; l+=32) { float e = expf(p4[warp][l]-m); p4[warp][l]=e; s+=e; }
#pragma unroll
        for (int o=16;o;o>>=1) s += __shfl_xor_sync(0xffffffffu, s, o);
        if (lane==0) invs[warp] = 1.f/s;
    }
    __syncthreads();
    float a0=0.f, a1=0.f, a2=0.f, a3=0.f;
    for (int l = warp; l < LL; l += 8) {
        float vv = g_qkv[(size_t)((b<<11)+l)*768 + 512 + (h<<5) + lane];
        a0 = fmaf(p4[0][l], vv, a0);
        a1 = fmaf(p4[1][l], vv, a1);
        a2 = fmaf(p4[2][l], vv, a2);
        a3 = fmaf(p4[3][l], vv, a3);
    }
    up[warp][0][lane]=a0; up[warp][1][lane]=a1; up[warp][2][lane]=a2; up[warp][3][lane]=a3;
    __syncthreads();
    if (warp < 4) {
        float s = 0.f;
#pragma unroll
        for (int w=0; w<8; w++) s += up[w][warp][lane];
        g_upd[((size_t)bh*UU + uc*4 + warp)*EE + lane] = s * invs[warp];
    }
}

__global__ void ctxfill_kernel()
{
    int i = blockIdx.x*blockDim.x + threadIdx.x;
    int e = i & 31; int h = (i>>5) & 7; int bl = i >> 8; int b = bl >> 11;
    g_ctx[i] = g_vmean[(b*8+h)*EE + e];
}

__global__ void scatter_kernel()
{
    int gb = blockIdx.x; int u = gb % UU; int bh = gb / UU; int b = bh>>3, h = bh&7;
    int tq = g_top[bh*UU+u];
    int e = threadIdx.x;
    g_ctx[(size_t)((b<<11)+tq)*DMM + (h<<5) + e] = g_upd[((size_t)bh*UU+u)*EE + e];
}

// ---------------- layernorm / ffn / distill ----------------
__device__ __forceinline__ float block_reduce_sum_256(float v, float* red)
{
    int lane = threadIdx.x & 31, warp = threadIdx.x >> 5;
#pragma unroll
    for (int o=16;o;o>>=1) v += __shfl_xor_sync(0xffffffffu, v, o);
    __syncthreads();
    if (lane==0) red[warp] = v;
    __syncthreads();
    float s = red[0];
#pragma unroll
    for (int w=1; w<8; w++) s += red[w];
    return s;
}

__global__ __launch_bounds__(256) void add_ln_kernel(
    const float* __restrict__ a, const float* __restrict__ res,
    const float* __restrict__ g, const float* __restrict__ beta,
    float* __restrict__ out)
{
    __shared__ float red[8];
    int row = blockIdx.x, t = threadIdx.x;
    float v = a[(size_t)row*DMM + t];
    if (res) v += res[(size_t)row*DMM + t];
    float mean = block_reduce_sum_256(v, red) * (1.f/256.f);
    float d = v - mean;
    float var = block_reduce_sum_256(d*d, red) * (1.f/256.f);
    out[(size_t)row*DMM + t] = d * rsqrtf(var + 1e-5f) * g[t] + beta[t];
}

__global__ __launch_bounds__(256) void ffn1_kernel(
    const float* __restrict__ w, const float* __restrict__ b1)
{
    __shared__ float xs[DMM];
    int row = blockIdx.x, t = threadIdx.x;
    xs[t] = g_x[(size_t)row*DMM + t];
    __syncthreads();
    int warp = t>>5, lane = t&31;
    for (int n = warp; n < NF; n += 8) {
        float acc = 0.f;
        const float* wr = w + (size_t)n*DMM;
        for (int k=lane; k<DMM; k+=32) acc = fmaf(xs[k], wr[k], acc);
#pragma unroll
        for (int o=16;o;o>>=1) acc += __shfl_xor_sync(0xffffffffu, acc, o);
        if (lane==0) g_y16[(size_t)row*NF + n] = fmaxf(acc + b1[n], 0.f);
    }
}

__global__ __launch_bounds__(256) void ffn2_ln_kernel(
    const float* __restrict__ w2, const float* __restrict__ b2,
    const float* __restrict__ g, const float* __restrict__ beta)
{
    __shared__ float ys[NF];
    __shared__ float red[8];
    int row = blockIdx.x, t = threadIdx.x;
    if (t < NF) ys[t] = g_y16[(size_t)row*NF + t];
    __syncthreads();
    float acc = b2[t];
    const float* wr = w2 + (size_t)t*NF;
#pragma unroll
    for (int f=0; f<NF; f++) acc = fmaf(ys[f], wr[f], acc);
    float v = g_x[(size_t)row*DMM + t] + acc;
    float mean = block_reduce_sum_256(v, red) * (1.f/256.f);
    float d = v - mean;
    float var = block_reduce_sum_256(d*d, red) * (1.f/256.f);
    g_x[(size_t)row*DMM + t] = d * rsqrtf(var + 1e-5f) * g[t] + beta[t];
}

__global__ void repack_kernel(const float* __restrict__ dcw)
{
    int i = blockIdx.x*blockDim.x + threadIdx.x;   // 3*65536
    if (i >= 3*DMM*DMM) return;
    int kk = i / (DMM*DMM); int rem = i % (DMM*DMM);
    int c = rem / DMM, ci = rem % DMM;
    g_wk[i] = dcw[(size_t)(c*DMM+ci)*3 + kk];
}

__global__ __launch_bounds__(256) void stats_kernel()
{
    __shared__ float red[8];
    int c = blockIdx.x, t = threadIdx.x;
    float s = 0.f, s2 = 0.f;
    for (int r=t; r<MTOT; r+=256) {
        float v = g_tmp[(size_t)r*DMM + c];
        s += v; s2 += v*v;
    }
    s  = block_reduce_sum_256(s,  red);
    s2 = block_reduce_sum_256(s2, red);
    if (t==0) {
        float m = s * (1.f/8192.f);
        float var = s2 * (1.f/8192.f) - m*m;
        g_stats[c] = m;
        g_stats[DMM + c] = rsqrtf(var + 1e-5f);
    }
}

__global__ void bn_elu_kernel(const float* __restrict__ g, const float* __restrict__ beta)
{
    int i = blockIdx.x*blockDim.x + threadIdx.x;
    int c = i & 255;
    float z = (g_tmp[i] - g_stats[c]) * g_stats[DMM+c] * g[c] + beta[c];
    g_x[i] = z > 0.f ? z : expm1f(z);
}

// ---------------- host orchestration ----------------
static float* symaddr(const void* sym) {
    void* p = nullptr;
    cudaGetSymbolAddress(&p, sym);
    return (float*)p;
}

extern "C" void kernel_launch(void* const* d_in, const int* in_sizes, int n_in,
                              void* d_out, int out_size)
{
    const float* x    = (const float*)d_in[0];
    const float* wq   = (const float*)d_in[1];
    const float* bq   = (const float*)d_in[2];
    const float* wk   = (const float*)d_in[3];
    const float* bk   = (const float*)d_in[4];
    const float* wv   = (const float*)d_in[5];
    const float* bv   = (const float*)d_in[6];
    const float* wo   = (const float*)d_in[7];
    const float* bo   = (const float*)d_in[8];
    const float* c1w  = (const float*)d_in[9];
    const float* c1b  = (const float*)d_in[10];
    const float* c2w  = (const float*)d_in[11];
    const float* c2b  = (const float*)d_in[12];
    const float* ln1g = (const float*)d_in[13];
    const float* ln1b = (const float*)d_in[14];
    const float* ln2g = (const float*)d_in[15];
    const float* ln2b = (const float*)d_in[16];
    const float* dcw  = (const float*)d_in[17];
    const float* dcb  = (const float*)d_in[18];
    const float* bng  = (const float*)d_in[19];
    const float* bnb  = (const float*)d_in[20];
    const float* fng  = (const float*)d_in[21];
    const float* fnb  = (const float*)d_in[22];

    float* gx    = symaddr(g_x);
    float* gqkv  = symaddr(g_qkv);
    float* gctx  = symaddr(g_ctx);
    float* gtmp  = symaddr(g_tmp);
    float* gwk   = symaddr(g_wk);
    float* gwqkv = symaddr(g_wqkv);
    float* gbqkv = symaddr(g_bqkv);

    cudaMemcpyAsync(gx, x, (size_t)MTOT*DMM*sizeof(float), cudaMemcpyDeviceToDevice, 0);
    pack_qkv<<<(NLAY*768*DMM+255)/256,256>>>(wq, wk, wv, bq, bk, bv);

    dim3 grid_qkv(768/BN2, MTOT/BM2);   // (12, 64)
    dim3 grid_256(DMM/BN2, MTOT/BM2);   // (4, 64)

    for (int i = 0; i < NLAY; i++) {
        size_t woff = (size_t)i*DMM*DMM, boff = (size_t)i*DMM;

        sgemm2<<<grid_qkv,256>>>(gx, gwqkv + (size_t)i*768*DMM, gbqkv + (size_t)i*768,
                                 gqkv, 1, 0);

        idx_kernel<<<(LL*UU+255)/256,256>>>(i);
        qkM_kernel<<<BB*HH*LL/8,256>>>();
        topk_kernel<<<BB*HH,256>>>();
        vmean_kernel<<<BB*HH,256>>>();
        attn_kernel4<<<BB*HH*10,256>>>();
        ctxfill_kernel<<<MTOT*DMM/256,256>>>();
        scatter_kernel<<<BB*HH*UU,32>>>();

        sgemm2<<<grid_256,256>>>(gctx, wo+woff, bo+boff, gtmp, 1, 0);
        add_ln_kernel<<<MTOT,256>>>(gx, gtmp, ln1g+boff, ln1b+boff, gx);

        ffn1_kernel<<<MTOT,256>>>(c1w + (size_t)i*NF*DMM, c1b + (size_t)i*NF);
        ffn2_ln_kernel<<<MTOT,256>>>(c2w + (size_t)i*DMM*NF, c2b+boff, ln2g+boff, ln2b+boff);

        if (i < NLAY-1) {
            repack_kernel<<<(3*DMM*DMM+255)/256,256>>>(dcw + (size_t)i*DMM*DMM*3);
            sgemm2<<<grid_256,256>>>(gx, gwk, dcb+boff, gtmp, 3, -1);
            stats_kernel<<<DMM,256>>>();
            bn_elu_kernel<<<MTOT*DMM/256,256>>>(bng+boff, bnb+boff);
        }
    }

    add_ln_kernel<<<MTOT,256>>>(gx, nullptr, fng, fnb, (float*)d_out);
}

// round 6
// speedup vs baseline: 1.2696x; 1.0014x over previous
#include <cuda_runtime.h>
#include <math.h>
#include <stdint.h>

#define BB   4
#define LL   2048
#define DMM  256
#define HH   8
#define EE   32
#define NLAY 3
#define NF   16
#define MTOT (BB*LL)      // 8192
#define UU   40

// ---------------- device scratch ----------------
__device__ float g_x   [MTOT*DMM];
__device__ float g_qkv [MTOT*768];      // fused q|k|v
__device__ float g_ctx [MTOT*DMM];
__device__ float g_tmp [MTOT*DMM];
__device__ float g_y16 [MTOT*NF];
__device__ int   g_idx [LL*UU];
__device__ float g_M   [BB*HH*LL];
__device__ int   g_top [BB*HH*UU];
__device__ float g_vmean[BB*HH*EE];
__device__ float g_upd [BB*HH*UU*EE];
__device__ float g_stats[2*DMM];
__device__ float g_wk  [3*DMM*DMM];
__device__ float g_wqkv[NLAY*768*DMM];
__device__ float g_bqkv[NLAY*768];

// ---------------- threefry2x32 (20 rounds) ----------------
__device__ __forceinline__ uint32_t rotl32(uint32_t v, int d){ return (v<<d)|(v>>(32-d)); }

__device__ __forceinline__ void tf2x32(uint32_t k0, uint32_t k1, uint32_t x0, uint32_t x1,
                                       uint32_t &o0, uint32_t &o1)
{
    uint32_t ks2 = k0 ^ k1 ^ 0x1BD11BDAu;
    x0 += k0; x1 += k1;
#define TFR(r) { x0 += x1; x1 = rotl32(x1,(r)); x1 ^= x0; }
    TFR(13) TFR(15) TFR(26) TFR(6)
    x0 += k1;  x1 += ks2 + 1u;
    TFR(17) TFR(29) TFR(16) TFR(24)
    x0 += ks2; x1 += k0 + 2u;
    TFR(13) TFR(15) TFR(26) TFR(6)
    x0 += k0;  x1 += k1 + 3u;
    TFR(17) TFR(29) TFR(16) TFR(24)
    x0 += k1;  x1 += ks2 + 4u;
    TFR(13) TFR(15) TFR(26) TFR(6)
    x0 += ks2; x1 += k0 + 5u;
#undef TFR
    o0 = x0; o1 = x1;
}

// partitionable threefry: bits[f] = o0^o1 of tf(k2,(0,f)); idx = bits & 2047
__global__ void idx_kernel(int layer)
{
    int f = blockIdx.x*blockDim.x + threadIdx.x;
    if (f >= LL*UU) return;
    uint32_t r0, r1, k2a, k2b, o0, o1;
    tf2x32(0u, 42u, 0u, (uint32_t)layer, r0, r1);
    tf2x32(r0, r1, 0u, 1u, k2a, k2b);
    tf2x32(k2a, k2b, 0u, (uint32_t)f, o0, o1);
    g_idx[f] = (int)((o0 ^ o1) & 2047u);
}

// ---------------- weight/bias packing for fused QKV ----------------
__global__ void pack_qkv(const float* __restrict__ wq, const float* __restrict__ wk,
                         const float* __restrict__ wv, const float* __restrict__ bq,
                         const float* __restrict__ bk, const float* __restrict__ bv)
{
    int i = blockIdx.x*blockDim.x + threadIdx.x;
    int total = NLAY*768*DMM;
    if (i < total) {
        int layer = i / (768*DMM);
        int rem = i % (768*DMM);
        int row = rem / DMM, col = rem % DMM;
        const float* src = row < 256 ? wq : (row < 512 ? wk : wv);
        g_wqkv[i] = src[(size_t)layer*DMM*DMM + (size_t)(row & 255)*DMM + col];
    }
    if (i < NLAY*768) {
        int layer = i / 768; int row = i % 768;
        const float* src = row < 256 ? bq : (row < 512 ? bk : bv);
        g_bqkv[i] = src[layer*DMM + (row & 255)];
    }
}

// ---------------- SGEMM v2: double-buffered, multi-pass (conv) --------------
// C[M, Nout] (+bias) = sum_p A_shift(p)[M,256] @ Wp[Nout,256]^T
// BM=128, BN=64, BK=16, 256 threads, 8x4 per-thread tile.
#define BM2 128
#define BN2 64
#define BK2 16

__global__ __launch_bounds__(256) void sgemm2(
    const float* __restrict__ A, const float* __restrict__ W,
    const float* __restrict__ bias, float* __restrict__ C,
    int npass, int shift_base)
{
    __shared__ float As[2][BK2][BM2+4];
    __shared__ float Bs[2][BK2][BN2+4];
    int ldc = gridDim.x * BN2;
    size_t pstr = (size_t)ldc * 256;    // pass stride in W
    int m0 = blockIdx.y * BM2;
    int n0 = blockIdx.x * BN2;
    int tid = threadIdx.x;
    int tx = tid & 15, ty = tid >> 4;

    int ar = tid >> 1;            // 0..127
    int ak = (tid & 1) * 4;       // 0 or 4
    int br = tid >> 2;            // 0..63
    int bk = (tid & 3) * 4;       // 0,4,8,12

    int mg = m0 + ar;
    int bbase = (mg >> 11) << 11;
    int lrow  = mg & 2047;
    const float* Wrow = W + (size_t)(n0 + br) * 256;

    float acc[8][4];
#pragma unroll
    for (int i=0;i<8;i++)
#pragma unroll
        for (int j=0;j<4;j++) acc[i][j] = 0.f;

    int NT = npass * 16;

    // prefetch tile 0
    float4 pa0, pa1, pb;
    {
        int p = 0, k0 = 0;
        const float* Ap = A + (size_t)(bbase + ((lrow + shift_base + p + 2048) & 2047)) * 256 + k0;
        pa0 = *(const float4*)(Ap + ak);
        pa1 = *(const float4*)(Ap + ak + 8);
        pb  = *(const float4*)(Wrow + (size_t)p*pstr + k0 + bk);
    }
    As[0][ak+0][ar]=pa0.x; As[0][ak+1][ar]=pa0.y; As[0][ak+2][ar]=pa0.z; As[0][ak+3][ar]=pa0.w;
    As[0][ak+8][ar]=pa1.x; As[0][ak+9][ar]=pa1.y; As[0][ak+10][ar]=pa1.z; As[0][ak+11][ar]=pa1.w;
    Bs[0][bk+0][br]=pb.x;  Bs[0][bk+1][br]=pb.y;  Bs[0][bk+2][br]=pb.z;  Bs[0][bk+3][br]=pb.w;
    __syncthreads();

    int s = 0;
    for (int t = 0; t < NT; t++) {
        float4 na0, na1, nb;
        bool more = (t+1 < NT);
        if (more) {
            int tt = t+1;
            int p = tt >> 4, k0 = (tt & 15) << 4;
            const float* Ap = A + (size_t)(bbase + ((lrow + shift_base + p + 2048) & 2047)) * 256 + k0;
            na0 = *(const float4*)(Ap + ak);
            na1 = *(const float4*)(Ap + ak + 8);
            nb  = *(const float4*)(Wrow + (size_t)p*pstr + k0 + bk);
        }
#pragma unroll
        for (int kk = 0; kk < BK2; kk++) {
            float4 a0 = *(const float4*)&As[s][kk][ty*8];
            float4 a1 = *(const float4*)&As[s][kk][ty*8+4];
            float4 b0 = *(const float4*)&Bs[s][kk][tx*4];
            float a[8] = {a0.x,a0.y,a0.z,a0.w,a1.x,a1.y,a1.z,a1.w};
            float b[4] = {b0.x,b0.y,b0.z,b0.w};
#pragma unroll
            for (int i=0;i<8;i++)
#pragma unroll
                for (int j=0;j<4;j++) acc[i][j] = fmaf(a[i], b[j], acc[i][j]);
        }
        if (more) {
            int sn = s ^ 1;
            As[sn][ak+0][ar]=na0.x; As[sn][ak+1][ar]=na0.y; As[sn][ak+2][ar]=na0.z; As[sn][ak+3][ar]=na0.w;
            As[sn][ak+8][ar]=na1.x; As[sn][ak+9][ar]=na1.y; As[sn][ak+10][ar]=na1.z; As[sn][ak+11][ar]=na1.w;
            Bs[sn][bk+0][br]=nb.x;  Bs[sn][bk+1][br]=nb.y;  Bs[sn][bk+2][br]=nb.z;  Bs[sn][bk+3][br]=nb.w;
            s = sn;
        }
        __syncthreads();
    }

    float4 bb = *(const float4*)(bias + n0 + tx*4);
#pragma unroll
    for (int i=0;i<8;i++) {
        int m = m0 + ty*8 + i;
        float4 v;
        v.x = acc[i][0] + bb.x;
        v.y = acc[i][1] + bb.y;
        v.z = acc[i][2] + bb.z;
        v.w = acc[i][3] + bb.w;
        *(float4*)(C + (size_t)m*ldc + n0 + tx*4) = v;
    }
}

// ---------------- attention pieces ----------------
// M[b,h,l] = max_u qk - sum_u qk / Lk ; one warp per (b,h,l)
__global__ __launch_bounds__(256) void qkM_kernel()
{
    int warp = threadIdx.x >> 5, lane = threadIdx.x & 31;
    int r = blockIdx.x*8 + warp;          // ((b*8+h)*2048+l)
    int b = r >> 14;
    int h = (r >> 11) & 7;
    int l = r & 2047;
    float qv = g_qkv[(size_t)((b<<11)+l)*768 + (h<<5) + lane];
    float mx = -1e30f, sm = 0.f;
#pragma unroll 4
    for (int u=0; u<UU; u++) {
        int ki = g_idx[l*UU+u];
        float kv = g_qkv[(size_t)((b<<11)+ki)*768 + 256 + (h<<5) + lane];
        float p = qv*kv;
#pragma unroll
        for (int o=16;o;o>>=1) p += __shfl_xor_sync(0xffffffffu, p, o);
        mx = fmaxf(mx, p);
        sm += p;
    }
    if (lane==0) g_M[r] = mx - sm*(1.f/2048.f);
}

// top-40 per (b,h): packed u64 argmax, ties -> lowest index
__global__ __launch_bounds__(256) void topk_kernel()
{
    int bh = blockIdx.x;
    __shared__ unsigned long long vals[LL];
    __shared__ unsigned long long wbest[8];
    int t = threadIdx.x, lane = t & 31, warp = t >> 5;
    for (int i=t; i<LL; i+=256) {
        unsigned u = __float_as_uint(g_M[(size_t)bh*LL + i]);
        u = u ^ ((u >> 31) ? 0xFFFFFFFFu : 0x80000000u);   // order-preserving map
        vals[i] = ((unsigned long long)u << 32) | (unsigned)(LL-1 - i);
    }
    __syncthreads();
    for (int it=0; it<UU; it++) {
        unsigned long long best = 0ull;
#pragma unroll
        for (int j=0;j<8;j++) {
            unsigned long long v = vals[t + j*256];
            best = v > best ? v : best;
        }
#pragma unroll
        for (int o=16;o;o>>=1) {
            unsigned long long v = __shfl_xor_sync(0xffffffffu, best, o);
            best = v > best ? v : best;
        }
        if (lane==0) wbest[warp] = best;
        __syncthreads();
        if (t==0) {
            unsigned long long b2 = wbest[0];
#pragma unroll
            for (int w=1; w<8; w++) b2 = wbest[w] > b2 ? wbest[w] : b2;
            int idx = (LL-1) - (int)(b2 & 0xFFFFFFFFu);
            g_top[bh*UU+it] = idx;
            vals[idx] = 0ull;
        }
        __syncthreads();
    }
}

__global__ __launch_bounds__(256) void vmean_kernel()
{
    int bh = blockIdx.x; int b = bh>>3, h = bh&7;
    int warp = threadIdx.x>>5, lane = threadIdx.x&31;
    __shared__ float accs[8][EE];
    float acc = 0.f;
    for (int l=warp; l<LL; l+=8)
        acc += g_qkv[(size_t)((b<<11)+l)*768 + 512 + (h<<5) + lane];
    accs[warp][lane] = acc;
    __syncthreads();
    if (warp==0) {
        float s = 0.f;
#pragma unroll
        for (int w=0; w<8; w++) s += accs[w][lane];
        g_vmean[bh*EE + lane] = s * (1.f/2048.f);
    }
}

// full attention for 4 selected queries per block: grid = 32 bh * 10 chunks
__global__ __launch_bounds__(256) void attn_kernel4()
{
    int gb = blockIdx.x;
    int uc = gb % 10; int bh = gb / 10; int b = bh>>3, h = bh&7;
    __shared__ float p4[4][LL];          // 32KB
    __shared__ float qs[4][EE];
    __shared__ float invs[4];
    __shared__ float up[8][4][EE];
    int t = threadIdx.x, warp = t>>5, lane = t&31;
    if (t < 128) {
        int qi = t >> 5;
        int tq = g_top[bh*UU + uc*4 + qi];
        qs[qi][lane] = g_qkv[(size_t)((b<<11)+tq)*768 + (h<<5) + lane];
    }
    __syncthreads();
    float q0 = qs[0][lane], q1 = qs[1][lane], q2 = qs[2][lane], q3 = qs[3][lane];
    const float scale = 0.17677669529663688f;   // 1/sqrt(32)
    for (int l = warp; l < LL; l += 8) {
        float kv = g_qkv[(size_t)((b<<11)+l)*768 + 256 + (h<<5) + lane];
        float s0 = q0*kv, s1 = q1*kv, s2 = q2*kv, s3 = q3*kv;
#pragma unroll
        for (int o=16;o;o>>=1) {
            s0 += __shfl_xor_sync(0xffffffffu, s0, o);
            s1 += __shfl_xor_sync(0xffffffffu, s1, o);
            s2 += __shfl_xor_sync(0xffffffffu, s2, o);
            s3 += __shfl_xor_sync(0xffffffffu, s3, o);
        }
        if (lane==0) { p4[0][l]=s0*scale; p4[1][l]=s1*scale; p4[2][l]=s2*scale; p4[3][l]=s3*scale; }
    }
    __syncthreads();
    if (warp < 4) {                       // softmax stats for query `warp`
        float m = -1e30f;
        for (int l=lane; l<LL; l+=32) m = fmaxf(m, p4[warp][l]);
#pragma unroll
        for (int o=16;o;o>>=1) m = fmaxf(m, __shfl_xor_sync(0xffffffffu, m, o));
        float s = 0.f;
        for (int l=lane; l<LL; l+=32) { float e = expf(p4[warp][l]-m); p4[warp][l]=e; s+=e; }
#pragma unroll
        for (int o=16;o;o>>=1) s += __shfl_xor_sync(0xffffffffu, s, o);
        if (lane==0) invs[warp] = 1.f/s;
    }
    __syncthreads();
    float a0=0.f, a1=0.f, a2=0.f, a3=0.f;
    for (int l = warp; l < LL; l += 8) {
        float vv = g_qkv[(size_t)((b<<11)+l)*768 + 512 + (h<<5) + lane];
        a0 = fmaf(p4[0][l], vv, a0);
        a1 = fmaf(p4[1][l], vv, a1);
        a2 = fmaf(p4[2][l], vv, a2);
        a3 = fmaf(p4[3][l], vv, a3);
    }
    up[warp][0][lane]=a0; up[warp][1][lane]=a1; up[warp][2][lane]=a2; up[warp][3][lane]=a3;
    __syncthreads();
    if (warp < 4) {
        float s = 0.f;
#pragma unroll
        for (int w=0; w<8; w++) s += up[w][warp][lane];
        g_upd[((size_t)bh*UU + uc*4 + warp)*EE + lane] = s * invs[warp];
    }
}

__global__ void ctxfill_kernel()
{
    int i = blockIdx.x*blockDim.x + threadIdx.x;
    int e = i & 31; int h = (i>>5) & 7; int bl = i >> 8; int b = bl >> 11;
    g_ctx[i] = g_vmean[(b*8+h)*EE + e];
}

__global__ void scatter_kernel()
{
    int gb = blockIdx.x; int u = gb % UU; int bh = gb / UU; int b = bh>>3, h = bh&7;
    int tq = g_top[bh*UU+u];
    int e = threadIdx.x;
    g_ctx[(size_t)((b<<11)+tq)*DMM + (h<<5) + e] = g_upd[((size_t)bh*UU+u)*EE + e];
}

// ---------------- layernorm / ffn / distill ----------------
__device__ __forceinline__ float block_reduce_sum_256(float v, float* red)
{
    int lane = threadIdx.x & 31, warp = threadIdx.x >> 5;
#pragma unroll
    for (int o=16;o;o>>=1) v += __shfl_xor_sync(0xffffffffu, v, o);
    __syncthreads();
    if (lane==0) red[warp] = v;
    __syncthreads();
    float s = red[0];
#pragma unroll
    for (int w=1; w<8; w++) s += red[w];
    return s;
}

__global__ __launch_bounds__(256) void add_ln_kernel(
    const float* __restrict__ a, const float* __restrict__ res,
    const float* __restrict__ g, const float* __restrict__ beta,
    float* __restrict__ out)
{
    __shared__ float red[8];
    int row = blockIdx.x, t = threadIdx.x;
    float v = a[(size_t)row*DMM + t];
    if (res) v += res[(size_t)row*DMM + t];
    float mean = block_reduce_sum_256(v, red) * (1.f/256.f);
    float d = v - mean;
    float var = block_reduce_sum_256(d*d, red) * (1.f/256.f);
    out[(size_t)row*DMM + t] = d * rsqrtf(var + 1e-5f) * g[t] + beta[t];
}

__global__ __launch_bounds__(256) void ffn1_kernel(
    const float* __restrict__ w, const float* __restrict__ b1)
{
    __shared__ float xs[DMM];
    int row = blockIdx.x, t = threadIdx.x;
    xs[t] = g_x[(size_t)row*DMM + t];
    __syncthreads();
    int warp = t>>5, lane = t&31;
    for (int n = warp; n < NF; n += 8) {
        float acc = 0.f;
        const float* wr = w + (size_t)n*DMM;
        for (int k=lane; k<DMM; k+=32) acc = fmaf(xs[k], wr[k], acc);
#pragma unroll
        for (int o=16;o;o>>=1) acc += __shfl_xor_sync(0xffffffffu, acc, o);
        if (lane==0) g_y16[(size_t)row*NF + n] = fmaxf(acc + b1[n], 0.f);
    }
}

__global__ __launch_bounds__(256) void ffn2_ln_kernel(
    const float* __restrict__ w2, const float* __restrict__ b2,
    const float* __restrict__ g, const float* __restrict__ beta)
{
    __shared__ float ys[NF];
    __shared__ float red[8];
    int row = blockIdx.x, t = threadIdx.x;
    if (t < NF) ys[t] = g_y16[(size_t)row*NF + t];
    __syncthreads();
    float acc = b2[t];
    const float* wr = w2 + (size_t)t*NF;
#pragma unroll
    for (int f=0; f<NF; f++) acc = fmaf(ys[f], wr[f], acc);
    float v = g_x[(size_t)row*DMM + t] + acc;
    float mean = block_reduce_sum_256(v, red) * (1.f/256.f);
    float d = v - mean;
    float var = block_reduce_sum_256(d*d, red) * (1.f/256.f);
    g_x[(size_t)row*DMM + t] = d * rsqrtf(var + 1e-5f) * g[t] + beta[t];
}

__global__ void repack_kernel(const float* __restrict__ dcw)
{
    int i = blockIdx.x*blockDim.x + threadIdx.x;   // 3*65536
    if (i >= 3*DMM*DMM) return;
    int kk = i / (DMM*DMM); int rem = i % (DMM*DMM);
    int c = rem / DMM, ci = rem % DMM;
    g_wk[i] = dcw[(size_t)(c*DMM+ci)*3 + kk];
}

__global__ __launch_bounds__(256) void stats_kernel()
{
    __shared__ float red[8];
    int c = blockIdx.x, t = threadIdx.x;
    float s = 0.f, s2 = 0.f;
    for (int r=t; r<MTOT; r+=256) {
        float v = g_tmp[(size_t)r*DMM + c];
        s += v; s2 += v*v;
    }
    s  = block_reduce_sum_256(s,  red);
    s2 = block_reduce_sum_256(s2, red);
    if (t==0) {
        float m = s * (1.f/8192.f);
        float var = s2 * (1.f/8192.f) - m*m;
        g_stats[c] = m;
        g_stats[DMM + c] = rsqrtf(var + 1e-5f);
    }
}

__global__ void bn_elu_kernel(const float* __restrict__ g, const float* __restrict__ beta)
{
    int i = blockIdx.x*blockDim.x + threadIdx.x;
    int c = i & 255;
    float z = (g_tmp[i] - g_stats[c]) * g_stats[DMM+c] * g[c] + beta[c];
    g_x[i] = z > 0.f ? z : expm1f(z);
}

// ---------------- host orchestration ----------------
static float* symaddr(const void* sym) {
    void* p = nullptr;
    cudaGetSymbolAddress(&p, sym);
    return (float*)p;
}

extern "C" void kernel_launch(void* const* d_in, const int* in_sizes, int n_in,
                              void* d_out, int out_size)
{
    const float* x    = (const float*)d_in[0];
    const float* wq   = (const float*)d_in[1];
    const float* bq   = (const float*)d_in[2];
    const float* wk   = (const float*)d_in[3];
    const float* bk   = (const float*)d_in[4];
    const float* wv   = (const float*)d_in[5];
    const float* bv   = (const float*)d_in[6];
    const float* wo   = (const float*)d_in[7];
    const float* bo   = (const float*)d_in[8];
    const float* c1w  = (const float*)d_in[9];
    const float* c1b  = (const float*)d_in[10];
    const float* c2w  = (const float*)d_in[11];
    const float* c2b  = (const float*)d_in[12];
    const float* ln1g = (const float*)d_in[13];
    const float* ln1b = (const float*)d_in[14];
    const float* ln2g = (const float*)d_in[15];
    const float* ln2b = (const float*)d_in[16];
    const float* dcw  = (const float*)d_in[17];
    const float* dcb  = (const float*)d_in[18];
    const float* bng  = (const float*)d_in[19];
    const float* bnb  = (const float*)d_in[20];
    const float* fng  = (const float*)d_in[21];
    const float* fnb  = (const float*)d_in[22];

    float* gx    = symaddr(g_x);
    float* gqkv  = symaddr(g_qkv);
    float* gctx  = symaddr(g_ctx);
    float* gtmp  = symaddr(g_tmp);
    float* gwk   = symaddr(g_wk);
    float* gwqkv = symaddr(g_wqkv);
    float* gbqkv = symaddr(g_bqkv);

    cudaMemcpyAsync(gx, x, (size_t)MTOT*DMM*sizeof(float), cudaMemcpyDeviceToDevice, 0);
    pack_qkv<<<(NLAY*768*DMM+255)/256,256>>>(wq, wk, wv, bq, bk, bv);

    dim3 grid_qkv(768/BN2, MTOT/BM2);   // (12, 64)
    dim3 grid_256(DMM/BN2, MTOT/BM2);   // (4, 64)

    for (int i = 0; i < NLAY; i++) {
        size_t woff = (size_t)i*DMM*DMM, boff = (size_t)i*DMM;

        sgemm2<<<grid_qkv,256>>>(gx, gwqkv + (size_t)i*768*DMM, gbqkv + (size_t)i*768,
                                 gqkv, 1, 0);

        idx_kernel<<<(LL*UU+255)/256,256>>>(i);
        qkM_kernel<<<BB*HH*LL/8,256>>>();
        topk_kernel<<<BB*HH,256>>>();
        vmean_kernel<<<BB*HH,256>>>();
        attn_kernel4<<<BB*HH*10,256>>>();
        ctxfill_kernel<<<MTOT*DMM/256,256>>>();
        scatter_kernel<<<BB*HH*UU,32>>>();

        sgemm2<<<grid_256,256>>>(gctx, wo+woff, bo+boff, gtmp, 1, 0);
        add_ln_kernel<<<MTOT,256>>>(gx, gtmp, ln1g+boff, ln1b+boff, gx);

        ffn1_kernel<<<MTOT,256>>>(c1w + (size_t)i*NF*DMM, c1b + (size_t)i*NF);
        ffn2_ln_kernel<<<MTOT,256>>>(c2w + (size_t)i*DMM*NF, c2b+boff, ln2g+boff, ln2b+boff);

        if (i < NLAY-1) {
            repack_kernel<<<(3*DMM*DMM+255)/256,256>>>(dcw + (size_t)i*DMM*DMM*3);
            sgemm2<<<grid_256,256>>>(gx, gwk, dcb+boff, gtmp, 3, -1);
            stats_kernel<<<DMM,256>>>();
            bn_elu_kernel<<<MTOT*DMM/256,256>>>(bng+boff, bnb+boff);
        }
    }

    add_ln_kernel<<<MTOT,256>>>(gx, nullptr, fng, fnb, (float*)d_out);
}

// round 7
// speedup vs baseline: 1.2715x; 1.0015x over previous
#include <cuda_runtime.h>
#include <math.h>
#include <stdint.h>

#define BB   4
#define LL   2048
#define DMM  256
#define HH   8
#define EE   32
#define NLAY 3
#define NF   16
#define MTOT (BB*LL)      // 8192
#define UU   40

// ---------------- device scratch ----------------
__device__ float g_x   [MTOT*DMM];
__device__ float g_qkv [MTOT*768];      // fused q|k|v
__device__ float g_ctx [MTOT*DMM];
__device__ float g_tmp [MTOT*DMM];
__device__ float g_y16 [MTOT*NF];
__device__ int   g_idx [LL*UU];
__device__ float g_M   [BB*HH*LL];
__device__ int   g_top [BB*HH*UU];
__device__ float g_vmean[BB*HH*EE];
__device__ float g_upd [BB*HH*UU*EE];
__device__ float g_stats[2*DMM];
__device__ float g_wk  [3*DMM*DMM];
__device__ float g_wqkv[NLAY*768*DMM];
__device__ float g_bqkv[NLAY*768];

// ---------------- threefry2x32 (20 rounds) ----------------
__device__ __forceinline__ uint32_t rotl32(uint32_t v, int d){ return (v<<d)|(v>>(32-d)); }

__device__ __forceinline__ void tf2x32(uint32_t k0, uint32_t k1, uint32_t x0, uint32_t x1,
                                       uint32_t &o0, uint32_t &o1)
{
    uint32_t ks2 = k0 ^ k1 ^ 0x1BD11BDAu;
    x0 += k0; x1 += k1;
#define TFR(r) { x0 += x1; x1 = rotl32(x1,(r)); x1 ^= x0; }
    TFR(13) TFR(15) TFR(26) TFR(6)
    x0 += k1;  x1 += ks2 + 1u;
    TFR(17) TFR(29) TFR(16) TFR(24)
    x0 += ks2; x1 += k0 + 2u;
    TFR(13) TFR(15) TFR(26) TFR(6)
    x0 += k0;  x1 += k1 + 3u;
    TFR(17) TFR(29) TFR(16) TFR(24)
    x0 += k1;  x1 += ks2 + 4u;
    TFR(13) TFR(15) TFR(26) TFR(6)
    x0 += ks2; x1 += k0 + 5u;
#undef TFR
    o0 = x0; o1 = x1;
}

// partitionable threefry: bits[f] = o0^o1 of tf(k2,(0,f)); idx = bits & 2047
__global__ void idx_kernel(int layer)
{
    int f = blockIdx.x*blockDim.x + threadIdx.x;
    if (f >= LL*UU) return;
    uint32_t r0, r1, k2a, k2b, o0, o1;
    tf2x32(0u, 42u, 0u, (uint32_t)layer, r0, r1);
    tf2x32(r0, r1, 0u, 1u, k2a, k2b);
    tf2x32(k2a, k2b, 0u, (uint32_t)f, o0, o1);
    g_idx[f] = (int)((o0 ^ o1) & 2047u);
}

// ---------------- weight/bias packing for fused QKV ----------------
__global__ void pack_qkv(const float* __restrict__ wq, const float* __restrict__ wk,
                         const float* __restrict__ wv, const float* __restrict__ bq,
                         const float* __restrict__ bk, const float* __restrict__ bv)
{
    int i = blockIdx.x*blockDim.x + threadIdx.x;
    int total = NLAY*768*DMM;
    if (i < total) {
        int layer = i / (768*DMM);
        int rem = i % (768*DMM);
        int row = rem / DMM, col = rem % DMM;
        const float* src = row < 256 ? wq : (row < 512 ? wk : wv);
        g_wqkv[i] = src[(size_t)layer*DMM*DMM + (size_t)(row & 255)*DMM + col];
    }
    if (i < NLAY*768) {
        int layer = i / 768; int row = i % 768;
        const float* src = row < 256 ? bq : (row < 512 ? bk : bv);
        g_bqkv[i] = src[layer*DMM + (row & 255)];
    }
}

// ---------------- SGEMM v2: double-buffered, multi-pass (conv) --------------
// C[M, Nout] (+bias) = sum_p A_shift(p)[M,256] @ Wp[Nout,256]^T
// BM=128, BN=64, BK=16, 256 threads, 8x4 per-thread tile.
#define BM2 128
#define BN2 64
#define BK2 16

__global__ __launch_bounds__(256) void sgemm2(
    const float* __restrict__ A, const float* __restrict__ W,
    const float* __restrict__ bias, float* __restrict__ C,
    int npass, int shift_base)
{
    __shared__ float As[2][BK2][BM2+4];
    __shared__ float Bs[2][BK2][BN2+4];
    int ldc = gridDim.x * BN2;
    size_t pstr = (size_t)ldc * 256;    // pass stride in W
    int m0 = blockIdx.y * BM2;
    int n0 = blockIdx.x * BN2;
    int tid = threadIdx.x;
    int tx = tid & 15, ty = tid >> 4;

    int ar = tid >> 1;            // 0..127
    int ak = (tid & 1) * 4;       // 0 or 4
    int br = tid >> 2;            // 0..63
    int bk = (tid & 3) * 4;       // 0,4,8,12

    int mg = m0 + ar;
    int bbase = (mg >> 11) << 11;
    int lrow  = mg & 2047;
    const float* Wrow = W + (size_t)(n0 + br) * 256;

    float acc[8][4];
#pragma unroll
    for (int i=0;i<8;i++)
#pragma unroll
        for (int j=0;j<4;j++) acc[i][j] = 0.f;

    int NT = npass * 16;

    // prefetch tile 0
    float4 pa0, pa1, pb;
    {
        int p = 0, k0 = 0;
        const float* Ap = A + (size_t)(bbase + ((lrow + shift_base + p + 2048) & 2047)) * 256 + k0;
        pa0 = *(const float4*)(Ap + ak);
        pa1 = *(const float4*)(Ap + ak + 8);
        pb  = *(const float4*)(Wrow + (size_t)p*pstr + k0 + bk);
    }
    As[0][ak+0][ar]=pa0.x; As[0][ak+1][ar]=pa0.y; As[0][ak+2][ar]=pa0.z; As[0][ak+3][ar]=pa0.w;
    As[0][ak+8][ar]=pa1.x; As[0][ak+9][ar]=pa1.y; As[0][ak+10][ar]=pa1.z; As[0][ak+11][ar]=pa1.w;
    Bs[0][bk+0][br]=pb.x;  Bs[0][bk+1][br]=pb.y;  Bs[0][bk+2][br]=pb.z;  Bs[0][bk+3][br]=pb.w;
    __syncthreads();

    int s = 0;
    for (int t = 0; t < NT; t++) {
        float4 na0, na1, nb;
        bool more = (t+1 < NT);
        if (more) {
            int tt = t+1;
            int p = tt >> 4, k0 = (tt & 15) << 4;
            const float* Ap = A + (size_t)(bbase + ((lrow + shift_base + p + 2048) & 2047)) * 256 + k0;
            na0 = *(const float4*)(Ap + ak);
            na1 = *(const float4*)(Ap + ak + 8);
            nb  = *(const float4*)(Wrow + (size_t)p*pstr + k0 + bk);
        }
#pragma unroll
        for (int kk = 0; kk < BK2; kk++) {
            float4 a0 = *(const float4*)&As[s][kk][ty*8];
            float4 a1 = *(const float4*)&As[s][kk][ty*8+4];
            float4 b0 = *(const float4*)&Bs[s][kk][tx*4];
            float a[8] = {a0.x,a0.y,a0.z,a0.w,a1.x,a1.y,a1.z,a1.w};
            float b[4] = {b0.x,b0.y,b0.z,b0.w};
#pragma unroll
            for (int i=0;i<8;i++)
#pragma unroll
                for (int j=0;j<4;j++) acc[i][j] = fmaf(a[i], b[j], acc[i][j]);
        }
        if (more) {
            int sn = s ^ 1;
            As[sn][ak+0][ar]=na0.x; As[sn][ak+1][ar]=na0.y; As[sn][ak+2][ar]=na0.z; As[sn][ak+3][ar]=na0.w;
            As[sn][ak+8][ar]=na1.x; As[sn][ak+9][ar]=na1.y; As[sn][ak+10][ar]=na1.z; As[sn][ak+11][ar]=na1.w;
            Bs[sn][bk+0][br]=nb.x;  Bs[sn][bk+1][br]=nb.y;  Bs[sn][bk+2][br]=nb.z;  Bs[sn][bk+3][br]=nb.w;
            s = sn;
        }
        __syncthreads();
    }

    float4 bb = *(const float4*)(bias + n0 + tx*4);
#pragma unroll
    for (int i=0;i<8;i++) {
        int m = m0 + ty*8 + i;
        float4 v;
        v.x = acc[i][0] + bb.x;
        v.y = acc[i][1] + bb.y;
        v.z = acc[i][2] + bb.z;
        v.w = acc[i][3] + bb.w;
        *(float4*)(C + (size_t)m*ldc + n0 + tx*4) = v;
    }
}

// ---------------- attention pieces ----------------
// M[b,h,l] = max_u qk - sum_u qk / Lk ; one warp per (b,h,l)
__global__ __launch_bounds__(256) void qkM_kernel()
{
    int warp = threadIdx.x >> 5, lane = threadIdx.x & 31;
    int r = blockIdx.x*8 + warp;          // ((b*8+h)*2048+l)
    int b = r >> 14;
    int h = (r >> 11) & 7;
    int l = r & 2047;
    float qv = g_qkv[(size_t)((b<<11)+l)*768 + (h<<5) + lane];
    float mx = -1e30f, sm = 0.f;
#pragma unroll 4
    for (int u=0; u<UU; u++) {
        int ki = g_idx[l*UU+u];
        float kv = g_qkv[(size_t)((b<<11)+ki)*768 + 256 + (h<<5) + lane];
        float p = qv*kv;
#pragma unroll
        for (int o=16;o;o>>=1) p += __shfl_xor_sync(0xffffffffu, p, o);
        mx = fmaxf(mx, p);
        sm += p;
    }
    if (lane==0) g_M[r] = mx - sm*(1.f/2048.f);
}

// top-40 per (b,h): packed u64 argmax, ties -> lowest index
__global__ __launch_bounds__(256) void topk_kernel()
{
    int bh = blockIdx.x;
    __shared__ unsigned long long vals[LL];
    __shared__ unsigned long long wbest[8];
    int t = threadIdx.x, lane = t & 31, warp = t >> 5;
    for (int i=t; i<LL; i+=256) {
        unsigned u = __float_as_uint(g_M[(size_t)bh*LL + i]);
        u = u ^ ((u >> 31) ? 0xFFFFFFFFu : 0x80000000u);   // order-preserving map
        vals[i] = ((unsigned long long)u << 32) | (unsigned)(LL-1 - i);
    }
    __syncthreads();
    for (int it=0; it<UU; it++) {
        unsigned long long best = 0ull;
#pragma unroll
        for (int j=0;j<8;j++) {
            unsigned long long v = vals[t + j*256];
            best = v > best ? v : best;
        }
#pragma unroll
        for (int o=16;o;o>>=1) {
            unsigned long long v = __shfl_xor_sync(0xffffffffu, best, o);
            best = v > best ? v : best;
        }
        if (lane==0) wbest[warp] = best;
        __syncthreads();
        if (t==0) {
            unsigned long long b2 = wbest[0];
#pragma unroll
            for (int w=1; w<8; w++) b2 = wbest[w] > b2 ? wbest[w] : b2;
            int idx = (LL-1) - (int)(b2 & 0xFFFFFFFFu);
            g_top[bh*UU+it] = idx;
            vals[idx] = 0ull;
        }
        __syncthreads();
    }
}

__global__ __launch_bounds__(256) void vmean_kernel()
{
    int bh = blockIdx.x; int b = bh>>3, h = bh&7;
    int warp = threadIdx.x>>5, lane = threadIdx.x&31;
    __shared__ float accs[8][EE];
    float acc = 0.f;
    for (int l=warp; l<LL; l+=8)
        acc += g_qkv[(size_t)((b<<11)+l)*768 + 512 + (h<<5) + lane];
    accs[warp][lane] = acc;
    __syncthreads();
    if (warp==0) {
        float s = 0.f;
#pragma unroll
        for (int w=0; w<8; w++) s += accs[w][lane];
        g_vmean[bh*EE + lane] = s * (1.f/2048.f);
    }
}

// full attention for 4 selected queries per block: grid = 32 bh * 10 chunks
__global__ __launch_bounds__(256) void attn_kernel4()
{
    int gb = blockIdx.x;
    int uc = gb % 10; int bh = gb / 10; int b = bh>>3, h = bh&7;
    __shared__ float p4[4][LL];          // 32KB
    __shared__ float qs[4][EE];
    __shared__ float invs[4];
    __shared__ float up[8][4][EE];
    int t = threadIdx.x, warp = t>>5, lane = t&31;
    if (t < 128) {
        int qi = t >> 5;
        int tq = g_top[bh*UU + uc*4 + qi];
        qs[qi][lane] = g_qkv[(size_t)((b<<11)+tq)*768 + (h<<5) + lane];
    }
    __syncthreads();
    float q0 = qs[0][lane], q1 = qs[1][lane], q2 = qs[2][lane], q3 = qs[3][lane];
    const float scale = 0.17677669529663688f;   // 1/sqrt(32)
    for (int l = warp; l < LL; l += 8) {
        float kv = g_qkv[(size_t)((b<<11)+l)*768 + 256 + (h<<5) + lane];
        float s0 = q0*kv, s1 = q1*kv, s2 = q2*kv, s3 = q3*kv;
#pragma unroll
        for (int o=16;o;o>>=1) {
            s0 += __shfl_xor_sync(0xffffffffu, s0, o);
            s1 += __shfl_xor_sync(0xffffffffu, s1, o);
            s2 += __shfl_xor_sync(0xffffffffu, s2, o);
            s3 += __shfl_xor_sync(0xffffffffu, s3, o);
        }
        if (lane==0) { p4[0][l]=s0*scale; p4[1][l]=s1*scale; p4[2][l]=s2*scale; p4[3][l]=s3*scale; }
    }
    __syncthreads();
    if (warp < 4) {                       // softmax stats for query `warp`
        float m = -1e30f;
        for (int l=lane; l<LL; l+=32) m = fmaxf(m, p4[warp][l]);
#pragma unroll
        for (int o=16;o;o>>=1) m = fmaxf(m, __shfl_xor_sync(0xffffffffu, m, o));
        float s = 0.f;
        for (int l=lane; l<LL; l+=32) { float e = expf(p4[warp][l]-m); p4[warp][l]=e; s+=e; }
#pragma unroll
        for (int o=16;o;o>>=1) s += __shfl_xor_sync(0xffffffffu, s, o);
        if (lane==0) invs[warp] = 1.f/s;
    }
    __syncthreads();
    float a0=0.f, a1=0.f, a2=0.f, a3=0.f;
    for (int l = warp; l < LL; l += 8) {
        float vv = g_qkv[(size_t)((b<<11)+l)*768 + 512 + (h<<5) + lane];
        a0 = fmaf(p4[0][l], vv, a0);
        a1 = fmaf(p4[1][l], vv, a1);
        a2 = fmaf(p4[2][l], vv, a2);
        a3 = fmaf(p4[3][l], vv, a3);
    }
    up[warp][0][lane]=a0; up[warp][1][lane]=a1; up[warp][2][lane]=a2; up[warp][3][lane]=a3;
    __syncthreads();
    if (warp < 4) {
        float s = 0.f;
#pragma unroll
        for (int w=0; w<8; w++) s += up[w][warp][lane];
        g_upd[((size_t)bh*UU + uc*4 + warp)*EE + lane] = s * invs[warp];
    }
}

__global__ void ctxfill_kernel()
{
    int i = blockIdx.x*blockDim.x + threadIdx.x;
    int e = i & 31; int h = (i>>5) & 7; int bl = i >> 8; int b = bl >> 11;
    g_ctx[i] = g_vmean[(b*8+h)*EE + e];
}

__global__ void scatter_kernel()
{
    int gb = blockIdx.x; int u = gb % UU; int bh = gb / UU; int b = bh>>3, h = bh&7;
    int tq = g_top[bh*UU+u];
    int e = threadIdx.x;
    g_ctx[(size_t)((b<<11)+tq)*DMM + (h<<5) + e] = g_upd[((size_t)bh*UU+u)*EE + e];
}

// ---------------- layernorm / ffn / distill ----------------
__device__ __forceinline__ float block_reduce_sum_256(float v, float* red)
{
    int lane = threadIdx.x & 31, warp = threadIdx.x >> 5;
#pragma unroll
    for (int o=16;o;o>>=1) v += __shfl_xor_sync(0xffffffffu, v, o);
    __syncthreads();
    if (lane==0) red[warp] = v;
    __syncthreads();
    float s = red[0];
#pragma unroll
    for (int w=1; w<8; w++) s += red[w];
    return s;
}

__global__ __launch_bounds__(256) void add_ln_kernel(
    const float* __restrict__ a, const float* __restrict__ res,
    const float* __restrict__ g, const float* __restrict__ beta,
    float* __restrict__ out)
{
    __shared__ float red[8];
    int row = blockIdx.x, t = threadIdx.x;
    float v = a[(size_t)row*DMM + t];
    if (res) v += res[(size_t)row*DMM + t];
    float mean = block_reduce_sum_256(v, red) * (1.f/256.f);
    float d = v - mean;
    float var = block_reduce_sum_256(d*d, red) * (1.f/256.f);
    out[(size_t)row*DMM + t] = d * rsqrtf(var + 1e-5f) * g[t] + beta[t];
}

__global__ __launch_bounds__(256) void ffn1_kernel(
    const float* __restrict__ w, const float* __restrict__ b1)
{
    __shared__ float xs[DMM];
    int row = blockIdx.x, t = threadIdx.x;
    xs[t] = g_x[(size_t)row*DMM + t];
    __syncthreads();
    int warp = t>>5, lane = t&31;
    for (int n = warp; n < NF; n += 8) {
        float acc = 0.f;
        const float* wr = w + (size_t)n*DMM;
        for (int k=lane; k<DMM; k+=32) acc = fmaf(xs[k], wr[k], acc);
#pragma unroll
        for (int o=16;o;o>>=1) acc += __shfl_xor_sync(0xffffffffu, acc, o);
        if (lane==0) g_y16[(size_t)row*NF + n] = fmaxf(acc + b1[n], 0.f);
    }
}

__global__ __launch_bounds__(256) void ffn2_ln_kernel(
    const float* __restrict__ w2, const float* __restrict__ b2,
    const float* __restrict__ g, const float* __restrict__ beta)
{
    __shared__ float ys[NF];
    __shared__ float red[8];
    int row = blockIdx.x, t = threadIdx.x;
    if (t < NF) ys[t] = g_y16[(size_t)row*NF + t];
    __syncthreads();
    float acc = b2[t];
    const float* wr = w2 + (size_t)t*NF;
#pragma unroll
    for (int f=0; f<NF; f++) acc = fmaf(ys[f], wr[f], acc);
    float v = g_x[(size_t)row*DMM + t] + acc;
    float mean = block_reduce_sum_256(v, red) * (1.f/256.f);
    float d = v - mean;
    float var = block_reduce_sum_256(d*d, red) * (1.f/256.f);
    g_x[(size_t)row*DMM + t] = d * rsqrtf(var + 1e-5f) * g[t] + beta[t];
}

__global__ void repack_kernel(const float* __restrict__ dcw)
{
    int i = blockIdx.x*blockDim.x + threadIdx.x;   // 3*65536
    if (i >= 3*DMM*DMM) return;
    int kk = i / (DMM*DMM); int rem = i % (DMM*DMM);
    int c = rem / DMM, ci = rem % DMM;
    g_wk[i] = dcw[(size_t)(c*DMM+ci)*3 + kk];
}

__global__ __launch_bounds__(256) void stats_kernel()
{
    __shared__ float red[8];
    int c = blockIdx.x, t = threadIdx.x;
    float s = 0.f, s2 = 0.f;
    for (int r=t; r<MTOT; r+=256) {
        float v = g_tmp[(size_t)r*DMM + c];
        s += v; s2 += v*v;
    }
    s  = block_reduce_sum_256(s,  red);
    s2 = block_reduce_sum_256(s2, red);
    if (t==0) {
        float m = s * (1.f/8192.f);
        float var = s2 * (1.f/8192.f) - m*m;
        g_stats[c] = m;
        g_stats[DMM + c] = rsqrtf(var + 1e-5f);
    }
}

__global__ void bn_elu_kernel(const float* __restrict__ g, const float* __restrict__ beta)
{
    int i = blockIdx.x*blockDim.x + threadIdx.x;
    int c = i & 255;
    float z = (g_tmp[i] - g_stats[c]) * g_stats[DMM+c] * g[c] + beta[c];
    g_x[i] = z > 0.f ? z : expm1f(z);
}

// ---------------- host orchestration ----------------
static float* symaddr(const void* sym) {
    void* p = nullptr;
    cudaGetSymbolAddress(&p, sym);
    return (float*)p;
}

extern "C" void kernel_launch(void* const* d_in, const int* in_sizes, int n_in,
                              void* d_out, int out_size)
{
    const float* x    = (const float*)d_in[0];
    const float* wq   = (const float*)d_in[1];
    const float* bq   = (const float*)d_in[2];
    const float* wk   = (const float*)d_in[3];
    const float* bk   = (const float*)d_in[4];
    const float* wv   = (const float*)d_in[5];
    const float* bv   = (const float*)d_in[6];
    const float* wo   = (const float*)d_in[7];
    const float* bo   = (const float*)d_in[8];
    const float* c1w  = (const float*)d_in[9];
    const float* c1b  = (const float*)d_in[10];
    const float* c2w  = (const float*)d_in[11];
    const float* c2b  = (const float*)d_in[12];
    const float* ln1g = (const float*)d_in[13];
    const float* ln1b = (const float*)d_in[14];
    const float* ln2g = (const float*)d_in[15];
    const float* ln2b = (const float*)d_in[16];
    const float* dcw  = (const float*)d_in[17];
    const float* dcb  = (const float*)d_in[18];
    const float* bng  = (const float*)d_in[19];
    const float* bnb  = (const float*)d_in[20];
    const float* fng  = (const float*)d_in[21];
    const float* fnb  = (const float*)d_in[22];

    float* gx    = symaddr(g_x);
    float* gqkv  = symaddr(g_qkv);
    float* gctx  = symaddr(g_ctx);
    float* gtmp  = symaddr(g_tmp);
    float* gwk   = symaddr(g_wk);
    float* gwqkv = symaddr(g_wqkv);
    float* gbqkv = symaddr(g_bqkv);

    cudaMemcpyAsync(gx, x, (size_t)MTOT*DMM*sizeof(float), cudaMemcpyDeviceToDevice, 0);
    pack_qkv<<<(NLAY*768*DMM+255)/256,256>>>(wq, wk, wv, bq, bk, bv);

    dim3 grid_qkv(768/BN2, MTOT/BM2);   // (12, 64)
    dim3 grid_256(DMM/BN2, MTOT/BM2);   // (4, 64)

    for (int i = 0; i < NLAY; i++) {
        size_t woff = (size_t)i*DMM*DMM, boff = (size_t)i*DMM;

        sgemm2<<<grid_qkv,256>>>(gx, gwqkv + (size_t)i*768*DMM, gbqkv + (size_t)i*768,
                                 gqkv, 1, 0);

        idx_kernel<<<(LL*UU+255)/256,256>>>(i);
        qkM_kernel<<<BB*HH*LL/8,256>>>();
        topk_kernel<<<BB*HH,256>>>();
        vmean_kernel<<<BB*HH,256>>>();
        attn_kernel4<<<BB*HH*10,256>>>();
        ctxfill_kernel<<<MTOT*DMM/256,256>>>();
        scatter_kernel<<<BB*HH*UU,32>>>();

        sgemm2<<<grid_256,256>>>(gctx, wo+woff, bo+boff, gtmp, 1, 0);
        add_ln_kernel<<<MTOT,256>>>(gx, gtmp, ln1g+boff, ln1b+boff, gx);

        ffn1_kernel<<<MTOT,256>>>(c1w + (size_t)i*NF*DMM, c1b + (size_t)i*NF);
        ffn2_ln_kernel<<<MTOT,256>>>(c2w + (size_t)i*DMM*NF, c2b+boff, ln2g+boff, ln2b+boff);

        if (i < NLAY-1) {
            repack_kernel<<<(3*DMM*DMM+255)/256,256>>>(dcw + (size_t)i*DMM*DMM*3);
            sgemm2<<<grid_256,256>>>(gx, gwk, dcb+boff, gtmp, 3, -1);
            stats_kernel<<<DMM,256>>>();
            bn_elu_kernel<<<MTOT*DMM/256,256>>>(bng+boff, bnb+boff);
        }
    }

    add_ln_kernel<<<MTOT,256>>>(gx, nullptr, fng, fnb, (float*)d_out);
}